// round 4
// baseline (speedup 1.0000x reference)
#include <cuda_runtime.h>
#include <cuda_bf16.h>
#include <math.h>

// Problem constants
#define BB   8
#define HH   128
#define WW   128
#define CIN  64
#define GG   2
#define GCH  32      // channels per group
#define SCH  288     // K*K*GC
#define GF   64      // filters per group
#define NP   (BB*HH*WW)   // 131072 pixels

// Scratch: offsets only (19 MB). g_samp eliminated.
__device__ float g_off[(size_t)GG * NP * 18];

// ===========================================================================
// Kernel 0: offset conv (3x3, 32 -> 18) per group.
// 32x32 pixel tile per block, 256 threads, 4 pixels per thread (amortizes
// warp-uniform weight broadcasts 4x). x staged in 2 channel chunks of 16.
// ===========================================================================
#define OHP   34                  // halo tile dim
#define XTS   17                  // padded channel stride (16 ch chunk + 1)
#define XT_F  (OHP*OHP*XTS)       // 19652 floats
#define WS_F  5760                // 9*32*20
#define OFF_SMEM_BYTES ((XT_F + WS_F + 32) * 4)

__global__ __launch_bounds__(256) void k_offsets(
    const float* __restrict__ x,      // [B,H,W,64]
    const float* __restrict__ off_w,  // [G,3,3,32,18]
    const float* __restrict__ off_b)  // [G,18]
{
    extern __shared__ float sm0[];
    float* xt   = sm0;                 // [pos][c pad 17]
    float* ws   = sm0 + XT_F;          // [t][c][j pad 20]
    float* wb   = sm0 + XT_F + WS_F;
    float* soff = sm0;                 // alias (xt dead after FMA loop)

    const int tid = threadIdx.x;
    const int z   = blockIdx.z;
    const int g   = z & 1;
    const int b   = z >> 1;
    const int ty0 = blockIdx.y * 32;
    const int tx0 = blockIdx.x * 32;

    for (int i = tid; i < WS_F; i += 256) {
        int r = i / 20, j = i % 20;
        ws[i] = (j < 18) ? off_w[(size_t)(g * 288 + r) * 18 + j] : 0.f;
    }
    if (tid < 18) wb[tid] = off_b[g * 18 + tid];

    const int px  = tid & 31;          // warp covers px 0..31 -> conflict-free
    const int py0 = tid >> 5;          // 0..7; pixels py0, py0+8, +16, +24

    float acc[4][18];
#pragma unroll
    for (int pp = 0; pp < 4; pp++)
#pragma unroll
        for (int j = 0; j < 18; j++) acc[pp][j] = 0.f;

    for (int cch = 0; cch < 2; cch++) {
        __syncthreads();
        // stage x chunk: 34x34 positions x 16 channels
        for (int i = tid; i < OHP * OHP * 16; i += 256) {
            int pos = i >> 4, c = i & 15;
            int hy = ty0 + pos / OHP - 1, hx = tx0 + pos % OHP - 1;
            float v = 0.f;
            if (hy >= 0 && hy < HH && hx >= 0 && hx < WW)
                v = x[((size_t)((b * HH + hy) * WW + hx)) * CIN
                      + g * GCH + cch * 16 + c];
            xt[pos * XTS + c] = v;
        }
        __syncthreads();

#pragma unroll 1
        for (int t = 0; t < 9; t++) {
            const int dy = t / 3, dx = t % 3;
            const float* wt = &ws[(t * 32 + cch * 16) * 20];
            const int base = (dy * OHP + px + dx) * XTS;
#pragma unroll 2
            for (int c = 0; c < 16; c++) {
                float v0 = xt[base + ((py0     ) * OHP) * XTS + c];
                float v1 = xt[base + ((py0 +  8) * OHP) * XTS + c];
                float v2 = xt[base + ((py0 + 16) * OHP) * XTS + c];
                float v3 = xt[base + ((py0 + 24) * OHP) * XTS + c];
                const float4* wv = (const float4*)&wt[c * 20];
                float4 w0 = wv[0], w1 = wv[1], w2 = wv[2], w3 = wv[3];
                float2 w4 = *(const float2*)&wt[c * 20 + 16];
#pragma unroll
                for (int pp = 0; pp < 4; pp++) {
                    float v = pp == 0 ? v0 : pp == 1 ? v1 : pp == 2 ? v2 : v3;
                    acc[pp][ 0] = fmaf(v, w0.x, acc[pp][ 0]);
                    acc[pp][ 1] = fmaf(v, w0.y, acc[pp][ 1]);
                    acc[pp][ 2] = fmaf(v, w0.z, acc[pp][ 2]);
                    acc[pp][ 3] = fmaf(v, w0.w, acc[pp][ 3]);
                    acc[pp][ 4] = fmaf(v, w1.x, acc[pp][ 4]);
                    acc[pp][ 5] = fmaf(v, w1.y, acc[pp][ 5]);
                    acc[pp][ 6] = fmaf(v, w1.z, acc[pp][ 6]);
                    acc[pp][ 7] = fmaf(v, w1.w, acc[pp][ 7]);
                    acc[pp][ 8] = fmaf(v, w2.x, acc[pp][ 8]);
                    acc[pp][ 9] = fmaf(v, w2.y, acc[pp][ 9]);
                    acc[pp][10] = fmaf(v, w2.z, acc[pp][10]);
                    acc[pp][11] = fmaf(v, w2.w, acc[pp][11]);
                    acc[pp][12] = fmaf(v, w3.x, acc[pp][12]);
                    acc[pp][13] = fmaf(v, w3.y, acc[pp][13]);
                    acc[pp][14] = fmaf(v, w3.z, acc[pp][14]);
                    acc[pp][15] = fmaf(v, w3.w, acc[pp][15]);
                    acc[pp][16] = fmaf(v, w4.x, acc[pp][16]);
                    acc[pp][17] = fmaf(v, w4.y, acc[pp][17]);
                }
            }
        }
    }
    __syncthreads();   // xt reads done; safe to overwrite with soff

#pragma unroll
    for (int pp = 0; pp < 4; pp++) {
        const int p = (py0 + pp * 8) * 32 + px;
#pragma unroll
        for (int j = 0; j < 18; j++)
            soff[p * 18 + j] = acc[pp][j] + wb[j];
    }
    __syncthreads();

    // coalesced write: each y-row = 32 px * 18 = 576 contiguous floats
    const size_t pbase = (size_t)b * (HH * WW) + (size_t)ty0 * WW + tx0;
    for (int i = tid; i < 32 * 32 * 18; i += 256) {
        int row = i / 576, rem = i % 576;
        g_off[((size_t)g * NP + pbase + (size_t)row * WW) * 18 + rem] = soff[i];
    }
}

// ===========================================================================
// Kernel 1: FUSED bilinear sampling + depthwise(3x3,groups=288) + pointwise.
// 8x8 tile per (b,g), 512 threads, 3 channel chunks of 96 (= 3 taps x 32ch).
// Sampling: warp-task = (halo pixel, tap); 4 coalesced 128B gathers from
// L2-resident x; writes samp chunk straight to smem. No g_samp round trip.
// ===========================================================================
#define CHUNK  96
#define C4     24                 // float4 per pixel per chunk
#define YP4    25                 // y row pad (float4)
#define SM_OFF  1800              // 100 px * 18 offsets
#define SM_HALO (100 * CHUNK)     // 9600 floats
#define SM_Y    (64 * YP4 * 4)    // 6400 floats
#define SM_PW   (64 * 100)        // 6400 floats [f][c pad 100]
#define SM_DW   (9 * CHUNK)       // 864 floats
#define SM_BYTES ((SM_OFF + SM_HALO + SM_Y + SM_PW + SM_DW) * 4)  // ~100.3KB
#define OUTP    68

__global__ __launch_bounds__(512, 2) void k_dwpw(
    const float* __restrict__ x,      // [B,H,W,64]
    const float* __restrict__ dw_w,   // [G,3,3,288,1]
    const float* __restrict__ dw_b,   // [G,288]
    const float* __restrict__ pw_w,   // [G,1,1,288,64]
    const float* __restrict__ pw_b,   // [G,64]
    float* __restrict__ out)          // [B,H,W,128]
{
    extern __shared__ float smem[];
    float* s_off  = smem;
    float* s_halo = smem + SM_OFF;
    float* s_y    = smem + SM_OFF + SM_HALO;
    float* s_pw   = smem + SM_OFF + SM_HALO + SM_Y;
    float* s_dw   = smem + SM_OFF + SM_HALO + SM_Y + SM_PW;
    float* s_red  = s_pw;                 // post-loop aliases
    float* s_out  = s_halo;

    const int tid = threadIdx.x;
    const int z   = blockIdx.z;
    const int g   = z & 1;
    const int b   = z >> 1;
    const int ty0 = blockIdx.y * 8;
    const int tx0 = blockIdx.x * 8;
    const int warp = tid >> 5, lane = tid & 31;

    // pw mapping: team 0/1 (even/odd c4), 4 filters x 4 pixels per thread
    const int team = tid >> 8;
    const int r    = tid & 255;
    const int fb   = (r >> 4) * 4;
    const int pq   = r & 15;

    float acc[16];
#pragma unroll
    for (int i = 0; i < 16; i++) acc[i] = 0.f;

    // --- load offsets for the 100 halo pixels (once) ---
    for (int i = tid; i < SM_OFF; i += 512) {
        int hp = i / 18, j = i % 18;
        int hy = ty0 + hp / 10 - 1, hx = tx0 + hp % 10 - 1;
        float v = 0.f;
        if (hy >= 0 && hy < HH && hx >= 0 && hx < WW)
            v = g_off[((size_t)g * NP + (size_t)((b * HH + hy) * WW + hx)) * 18 + j];
        s_off[i] = v;
    }

    float4* t4  = (float4*)s_halo;
    float4* y4p = (float4*)s_y;
    float4* d4  = (float4*)s_dw;
    const size_t xbase = (size_t)b * (HH * WW) * CIN + g * GCH + lane;

    for (int cc = 0; cc < 3; cc++) {
        const int cbase = cc * CHUNK;
        __syncthreads();

        // --- sample halo chunk directly into smem: 100 px x 3 taps ---
        for (int i = warp; i < 300; i += 16) {
            const int hp = i / 3, kl = i - hp * 3;
            const int hy = ty0 + hp / 10 - 1, hx = tx0 + hp % 10 - 1;
            float* dst = &s_halo[hp * CHUNK + kl * 32 + lane];
            if (hy < 0 || hy >= HH || hx < 0 || hx >= WW) { *dst = 0.f; continue; }
            const int k = cc * 3 + kl;
            float ox = s_off[hp * 18 + 2 * k];
            float oy = s_off[hp * 18 + 2 * k + 1];
            float lx = (float)hx + (float)(k % 3 - 1) + ox;
            float ly = (float)hy + (float)(k / 3 - 1) + oy;
            lx = fminf(fmaxf(lx, 0.f), 127.f);
            ly = fminf(fmaxf(ly, 0.f), 127.f);
            float x0f = fminf(fmaxf(floorf(lx), 0.f), 127.f);
            float y0f = fminf(fmaxf(floorf(ly), 0.f), 127.f);
            float x1f = fminf(x0f + 1.f, 127.f);
            float y1f = fminf(y0f + 1.f, 127.f);
            int x0 = (int)x0f, x1 = (int)x1f, y0 = (int)y0f, y1 = (int)y1f;
            float dx1 = x1f - lx, dx0 = lx - x0f;
            float dy1 = y1f - ly, dy0 = ly - y0f;
            float Ia = x[xbase + (size_t)(y0 * WW + x0) * CIN];
            float Ib = x[xbase + (size_t)(y1 * WW + x0) * CIN];
            float Ic = x[xbase + (size_t)(y0 * WW + x1) * CIN];
            float Id = x[xbase + (size_t)(y1 * WW + x1) * CIN];
            *dst = dx1 * dy1 * Ia + dx1 * dy0 * Ib
                 + dx0 * dy1 * Ic + dx0 * dy0 * Id;
        }
        // --- stage dw + pw weights for this chunk (independent smem) ---
        for (int i = tid; i < 9 * C4; i += 512) {
            int t = i / C4, c4 = i % C4;
            d4[i] = __ldg((const float4*)&dw_w[(size_t)g * 2592 + t * SCH
                                               + cbase + c4 * 4]);
        }
        for (int i = tid; i < CHUNK * 64; i += 512) {
            int c = i >> 6, f = i & 63;
            s_pw[f * 100 + c] =
                pw_w[(size_t)g * (SCH * GF) + (size_t)(cbase + c) * 64 + f];
        }
        __syncthreads();

        // --- depthwise 3x3: 2x1 pixel-pair register blocking ---
        for (int i = tid; i < 768; i += 512) {
            int c4 = i % C4;
            int pair = i / C4;
            int py = pair >> 2, qx = (pair & 3) * 2;
            float4 bias = __ldg((const float4*)&dw_b[g * SCH + cbase + c4 * 4]);
            float4 a0 = bias, a1 = bias;
#pragma unroll
            for (int ty = 0; ty < 3; ty++) {
                const float4* vr = &t4[((py + ty) * 10 + qx) * C4 + c4];
                float4 v0 = vr[0], v1 = vr[C4], v2 = vr[2*C4], v3 = vr[3*C4];
                float4 w0 = d4[(ty*3+0)*C4 + c4];
                float4 w1 = d4[(ty*3+1)*C4 + c4];
                float4 w2 = d4[(ty*3+2)*C4 + c4];
                a0.x = fmaf(w0.x,v0.x,fmaf(w1.x,v1.x,fmaf(w2.x,v2.x,a0.x)));
                a0.y = fmaf(w0.y,v0.y,fmaf(w1.y,v1.y,fmaf(w2.y,v2.y,a0.y)));
                a0.z = fmaf(w0.z,v0.z,fmaf(w1.z,v1.z,fmaf(w2.z,v2.z,a0.z)));
                a0.w = fmaf(w0.w,v0.w,fmaf(w1.w,v1.w,fmaf(w2.w,v2.w,a0.w)));
                a1.x = fmaf(w0.x,v1.x,fmaf(w1.x,v2.x,fmaf(w2.x,v3.x,a1.x)));
                a1.y = fmaf(w0.y,v1.y,fmaf(w1.y,v2.y,fmaf(w2.y,v3.y,a1.y)));
                a1.z = fmaf(w0.z,v1.z,fmaf(w1.z,v2.z,fmaf(w2.z,v3.z,a1.z)));
                a1.w = fmaf(w0.w,v1.w,fmaf(w1.w,v2.w,fmaf(w2.w,v3.w,a1.w)));
            }
            y4p[(py * 8 + qx) * YP4 + c4]     = a0;
            y4p[(py * 8 + qx + 1) * YP4 + c4] = a1;
        }
        __syncthreads();

        // --- pointwise accumulate: this team's c4 slice ---
#pragma unroll 3
        for (int s = 0; s < C4; s += 2) {
            const int c4 = s + team;
            float4 y0 = y4p[(pq +  0) * YP4 + c4];
            float4 y1 = y4p[(pq + 16) * YP4 + c4];
            float4 y2 = y4p[(pq + 32) * YP4 + c4];
            float4 y3 = y4p[(pq + 48) * YP4 + c4];
#pragma unroll
            for (int k = 0; k < 4; k++) {
                float4 w = *(const float4*)&s_pw[(fb + k) * 100 + c4 * 4];
                acc[k*4+0] = fmaf(y0.x,w.x,fmaf(y0.y,w.y,fmaf(y0.z,w.z,fmaf(y0.w,w.w,acc[k*4+0]))));
                acc[k*4+1] = fmaf(y1.x,w.x,fmaf(y1.y,w.y,fmaf(y1.z,w.z,fmaf(y1.w,w.w,acc[k*4+1]))));
                acc[k*4+2] = fmaf(y2.x,w.x,fmaf(y2.y,w.y,fmaf(y2.z,w.z,fmaf(y2.w,w.w,acc[k*4+2]))));
                acc[k*4+3] = fmaf(y3.x,w.x,fmaf(y3.y,w.y,fmaf(y3.z,w.z,fmaf(y3.w,w.w,acc[k*4+3]))));
            }
        }
    }
    __syncthreads();

    // split-K reduce + biased output staging
    if (team == 1) {
#pragma unroll
        for (int i = 0; i < 16; i++) s_red[r * 16 + i] = acc[i];
    }
    __syncthreads();
    if (team == 0) {
#pragma unroll
        for (int k = 0; k < 4; k++) {
            const float bias = __ldg(&pw_b[g * GF + fb + k]);
#pragma unroll
            for (int i = 0; i < 4; i++) {
                int p = pq + 16 * i;
                s_out[p * OUTP + fb + k] = acc[k*4+i] + s_red[r*16 + k*4+i] + bias;
            }
        }
    }
    __syncthreads();

    for (int i = tid; i < 4096; i += 512) {
        int p = i >> 6, f = i & 63;
        int py = p >> 3, px = p & 7;
        out[((size_t)((b * HH + ty0 + py) * WW) + tx0 + px) * (GG * GF)
            + g * GF + f] = s_out[p * OUTP + f];
    }
}

// ---------------------------------------------------------------------------
extern "C" void kernel_launch(void* const* d_in, const int* in_sizes, int n_in,
                              void* d_out, int out_size)
{
    const float* x     = (const float*)d_in[0];
    const float* off_w = (const float*)d_in[1];
    const float* off_b = (const float*)d_in[2];
    const float* dw_w  = (const float*)d_in[3];
    const float* dw_b  = (const float*)d_in[4];
    const float* pw_w  = (const float*)d_in[5];
    const float* pw_b  = (const float*)d_in[6];
    float* out = (float*)d_out;

    cudaFuncSetAttribute(k_offsets, cudaFuncAttributeMaxDynamicSharedMemorySize,
                         OFF_SMEM_BYTES);
    cudaFuncSetAttribute(k_dwpw, cudaFuncAttributeMaxDynamicSharedMemorySize,
                         SM_BYTES);

    k_offsets<<<dim3(WW/32, HH/32, BB*GG), 256, OFF_SMEM_BYTES>>>(x, off_w, off_b);
    k_dwpw<<<dim3(WW / 8, HH / 8, BB * GG), 512, SM_BYTES>>>(
        x, dw_w, dw_b, pw_w, pw_b, out);
}

// round 6
// speedup vs baseline: 1.3514x; 1.3514x over previous
#include <cuda_runtime.h>
#include <cuda_bf16.h>
#include <math.h>

// Problem constants
#define BB   8
#define HH   128
#define WW   128
#define CIN  64
#define GG   2
#define GCH  32      // channels per group
#define SCH  288     // K*K*GC
#define GF   64      // filters per group
#define NP   (BB*HH*WW)   // 131072 pixels

// Scratch
__device__ float g_samp[(size_t)GG * NP * SCH];   // sampled field   (302 MB)
__device__ float g_off [(size_t)GG * NP * 18];    // offsets         (19 MB)

// ===========================================================================
// Kernel 0: offset conv (3x3, 32 -> 18) per group.
// 32x32 pixel tile per block, 256 threads, 4 pixels per thread (amortizes
// warp-uniform weight broadcasts 4x). x staged in 2 channel chunks of 16.
// ===========================================================================
#define OHP   34                  // halo tile dim
#define XTS   17                  // padded channel stride (16 ch chunk + 1)
#define XT_F  (OHP*OHP*XTS)       // 19652 floats
#define WS_F  5760                // 9*32*20
#define OFF_SMEM_BYTES ((XT_F + WS_F + 32) * 4)

__global__ __launch_bounds__(256) void k_offsets(
    const float* __restrict__ x,      // [B,H,W,64]
    const float* __restrict__ off_w,  // [G,3,3,32,18]
    const float* __restrict__ off_b)  // [G,18]
{
    extern __shared__ float sm0[];
    float* xt   = sm0;                 // [pos][c pad 17]
    float* ws   = sm0 + XT_F;          // [t][c][j pad 20]
    float* wb   = sm0 + XT_F + WS_F;
    float* soff = sm0;                 // alias (xt dead after FMA loop)

    const int tid = threadIdx.x;
    const int z   = blockIdx.z;
    const int g   = z & 1;
    const int b   = z >> 1;
    const int ty0 = blockIdx.y * 32;
    const int tx0 = blockIdx.x * 32;

    for (int i = tid; i < WS_F; i += 256) {
        int r = i / 20, j = i % 20;
        ws[i] = (j < 18) ? off_w[(size_t)(g * 288 + r) * 18 + j] : 0.f;
    }
    if (tid < 18) wb[tid] = off_b[g * 18 + tid];

    const int px  = tid & 31;
    const int py0 = tid >> 5;          // pixels py0, +8, +16, +24

    float acc[4][18];
#pragma unroll
    for (int pp = 0; pp < 4; pp++)
#pragma unroll
        for (int j = 0; j < 18; j++) acc[pp][j] = 0.f;

    for (int cch = 0; cch < 2; cch++) {
        __syncthreads();
        for (int i = tid; i < OHP * OHP * 16; i += 256) {
            int pos = i >> 4, c = i & 15;
            int hy = ty0 + pos / OHP - 1, hx = tx0 + pos % OHP - 1;
            float v = 0.f;
            if (hy >= 0 && hy < HH && hx >= 0 && hx < WW)
                v = x[((size_t)((b * HH + hy) * WW + hx)) * CIN
                      + g * GCH + cch * 16 + c];
            xt[pos * XTS + c] = v;
        }
        __syncthreads();

#pragma unroll 1
        for (int t = 0; t < 9; t++) {
            const int dy = t / 3, dx = t % 3;
            const float* wt = &ws[(t * 32 + cch * 16) * 20];
            const int base = (dy * OHP + px + dx) * XTS;
#pragma unroll 2
            for (int c = 0; c < 16; c++) {
                float v0 = xt[base + ((py0     ) * OHP) * XTS + c];
                float v1 = xt[base + ((py0 +  8) * OHP) * XTS + c];
                float v2 = xt[base + ((py0 + 16) * OHP) * XTS + c];
                float v3 = xt[base + ((py0 + 24) * OHP) * XTS + c];
                const float4* wv = (const float4*)&wt[c * 20];
                float4 w0 = wv[0], w1 = wv[1], w2 = wv[2], w3 = wv[3];
                float2 w4 = *(const float2*)&wt[c * 20 + 16];
#pragma unroll
                for (int pp = 0; pp < 4; pp++) {
                    float v = pp == 0 ? v0 : pp == 1 ? v1 : pp == 2 ? v2 : v3;
                    acc[pp][ 0] = fmaf(v, w0.x, acc[pp][ 0]);
                    acc[pp][ 1] = fmaf(v, w0.y, acc[pp][ 1]);
                    acc[pp][ 2] = fmaf(v, w0.z, acc[pp][ 2]);
                    acc[pp][ 3] = fmaf(v, w0.w, acc[pp][ 3]);
                    acc[pp][ 4] = fmaf(v, w1.x, acc[pp][ 4]);
                    acc[pp][ 5] = fmaf(v, w1.y, acc[pp][ 5]);
                    acc[pp][ 6] = fmaf(v, w1.z, acc[pp][ 6]);
                    acc[pp][ 7] = fmaf(v, w1.w, acc[pp][ 7]);
                    acc[pp][ 8] = fmaf(v, w2.x, acc[pp][ 8]);
                    acc[pp][ 9] = fmaf(v, w2.y, acc[pp][ 9]);
                    acc[pp][10] = fmaf(v, w2.z, acc[pp][10]);
                    acc[pp][11] = fmaf(v, w2.w, acc[pp][11]);
                    acc[pp][12] = fmaf(v, w3.x, acc[pp][12]);
                    acc[pp][13] = fmaf(v, w3.y, acc[pp][13]);
                    acc[pp][14] = fmaf(v, w3.z, acc[pp][14]);
                    acc[pp][15] = fmaf(v, w3.w, acc[pp][15]);
                    acc[pp][16] = fmaf(v, w4.x, acc[pp][16]);
                    acc[pp][17] = fmaf(v, w4.y, acc[pp][17]);
                }
            }
        }
    }
    __syncthreads();   // xt reads done; safe to overwrite with soff

#pragma unroll
    for (int pp = 0; pp < 4; pp++) {
        const int p = (py0 + pp * 8) * 32 + px;
#pragma unroll
        for (int j = 0; j < 18; j++)
            soff[p * 18 + j] = acc[pp][j] + wb[j];
    }
    __syncthreads();

    const size_t pbase = (size_t)b * (HH * WW) + (size_t)ty0 * WW + tx0;
    for (int i = tid; i < 32 * 32 * 18; i += 256) {
        int row = i / 576, rem = i % 576;
        g_off[((size_t)g * NP + pbase + (size_t)row * WW) * 18 + rem] = soff[i];
    }
}

// ===========================================================================
// Kernel 1: bilinear sampling. One warp per (pixel, group). lane = channel.
// ===========================================================================
__global__ __launch_bounds__(256) void k_sample(
    const float* __restrict__ x)      // [B,H,W,64]
{
    const int tid  = threadIdx.x;
    const int g    = blockIdx.y;
    const int warp = tid >> 5, lane = tid & 31;
    const int p   = blockIdx.x * 8 + warp;
    const int b   = p >> 14;
    const int rem = p & 16383;
    const int yy  = rem >> 7;
    const int xx  = rem & 127;

    float offv = 0.f;
    if (lane < 18) offv = g_off[((size_t)g * NP + p) * 18 + lane];

    const size_t xbase = (size_t)b * (HH * WW) * CIN + g * GCH + lane;
    float* outp = &g_samp[((size_t)g * NP + p) * SCH + lane];
#pragma unroll
    for (int k = 0; k < 9; k++) {
        float ox = __shfl_sync(0xffffffffu, offv, 2 * k);
        float oy = __shfl_sync(0xffffffffu, offv, 2 * k + 1);
        float lx = (float)xx + (float)(k % 3 - 1) + ox;
        float ly = (float)yy + (float)(k / 3 - 1) + oy;
        lx = fminf(fmaxf(lx, 0.f), 127.f);
        ly = fminf(fmaxf(ly, 0.f), 127.f);
        float x0f = fminf(fmaxf(floorf(lx), 0.f), 127.f);
        float y0f = fminf(fmaxf(floorf(ly), 0.f), 127.f);
        float x1f = fminf(x0f + 1.f, 127.f);
        float y1f = fminf(y0f + 1.f, 127.f);
        int x0 = (int)x0f, x1 = (int)x1f, y0 = (int)y0f, y1 = (int)y1f;
        float dx1 = x1f - lx, dx0 = lx - x0f;
        float dy1 = y1f - ly, dy0 = ly - y0f;
        float Ia = x[xbase + (size_t)(y0 * WW + x0) * CIN];
        float Ib = x[xbase + (size_t)(y1 * WW + x0) * CIN];
        float Ic = x[xbase + (size_t)(y0 * WW + x1) * CIN];
        float Id = x[xbase + (size_t)(y1 * WW + x1) * CIN];
        outp[k * 32] = dx1 * dy1 * Ia + dx1 * dy0 * Ib
                     + dx0 * dy1 * Ic + dx0 * dy0 * Id;
    }
}

// ===========================================================================
// Kernel 2: fused depthwise(3x3, groups=288) + pointwise(288->64).
// 8x8 tile per (b,g), 512 threads, 3 channel chunks of 96.
// dw: 2x1 pixel-pair register blocking. pw: split-K, 4f x 4px x 16 accs/thread.
// ===========================================================================
#define CHUNK  96
#define C4     24                 // float4 per pixel per chunk
#define YP4    25                 // y row pad (float4)
#define SM_HALO (100 * CHUNK)     // 9600 floats
#define SM_Y    (64 * YP4 * 4)    // 6400 floats
#define SM_PW   (64 * 100)        // 6400 floats [f][c pad 100]
#define SM_DW   (9 * CHUNK)       // 864 floats
#define SM_BYTES ((SM_HALO + SM_Y + SM_PW + SM_DW) * 4)
#define OUTP    68

__global__ __launch_bounds__(512, 2) void k_dwpw(
    const float* __restrict__ dw_w,   // [G,3,3,288,1]
    const float* __restrict__ dw_b,   // [G,288]
    const float* __restrict__ pw_w,   // [G,1,1,288,64]
    const float* __restrict__ pw_b,   // [G,64]
    float* __restrict__ out)          // [B,H,W,128]
{
    extern __shared__ float smem[];
    float* s_halo = smem;
    float* s_y    = smem + SM_HALO;
    float* s_pw   = smem + SM_HALO + SM_Y;
    float* s_dw   = smem + SM_HALO + SM_Y + SM_PW;
    float* s_red  = s_pw;                 // post-loop aliases
    float* s_out  = s_halo;

    const int tid = threadIdx.x;
    const int z   = blockIdx.z;
    const int g   = z & 1;
    const int b   = z >> 1;
    const int ty0 = blockIdx.y * 8;
    const int tx0 = blockIdx.x * 8;

    const int team = tid >> 8;
    const int r    = tid & 255;
    const int fb   = (r >> 4) * 4;
    const int pq   = r & 15;

    float acc[16];
#pragma unroll
    for (int i = 0; i < 16; i++) acc[i] = 0.f;

    float4* t4  = (float4*)s_halo;
    float4* y4p = (float4*)s_y;
    float4* d4  = (float4*)s_dw;

    for (int cc = 0; cc < 3; cc++) {
        const int cbase = cc * CHUNK;
        __syncthreads();

        for (int i = tid; i < 100 * C4; i += 512) {
            int hp = i / C4, c4 = i % C4;
            int hy = ty0 + hp / 10 - 1, hx = tx0 + hp % 10 - 1;
            float4 v = make_float4(0.f, 0.f, 0.f, 0.f);
            if (hy >= 0 && hy < HH && hx >= 0 && hx < WW)
                v = *(const float4*)&g_samp[((size_t)g * NP +
                        (size_t)((b * HH + hy) * WW + hx)) * SCH + cbase + c4 * 4];
            t4[i] = v;
        }
        for (int i = tid; i < 9 * C4; i += 512) {
            int t = i / C4, c4 = i % C4;
            d4[i] = __ldg((const float4*)&dw_w[(size_t)g * 2592 + t * SCH
                                               + cbase + c4 * 4]);
        }
        for (int i = tid; i < CHUNK * 64; i += 512) {
            int c = i >> 6, f = i & 63;
            s_pw[f * 100 + c] =
                pw_w[(size_t)g * (SCH * GF) + (size_t)(cbase + c) * 64 + f];
        }
        __syncthreads();

        for (int i = tid; i < 768; i += 512) {
            int c4 = i % C4;
            int pair = i / C4;
            int py = pair >> 2, qx = (pair & 3) * 2;
            float4 bias = __ldg((const float4*)&dw_b[g * SCH + cbase + c4 * 4]);
            float4 a0 = bias, a1 = bias;
#pragma unroll
            for (int ty = 0; ty < 3; ty++) {
                const float4* vr = &t4[((py + ty) * 10 + qx) * C4 + c4];
                float4 v0 = vr[0], v1 = vr[C4], v2 = vr[2*C4], v3 = vr[3*C4];
                float4 w0 = d4[(ty*3+0)*C4 + c4];
                float4 w1 = d4[(ty*3+1)*C4 + c4];
                float4 w2 = d4[(ty*3+2)*C4 + c4];
                a0.x = fmaf(w0.x,v0.x,fmaf(w1.x,v1.x,fmaf(w2.x,v2.x,a0.x)));
                a0.y = fmaf(w0.y,v0.y,fmaf(w1.y,v1.y,fmaf(w2.y,v2.y,a0.y)));
                a0.z = fmaf(w0.z,v0.z,fmaf(w1.z,v1.z,fmaf(w2.z,v2.z,a0.z)));
                a0.w = fmaf(w0.w,v0.w,fmaf(w1.w,v1.w,fmaf(w2.w,v2.w,a0.w)));
                a1.x = fmaf(w0.x,v1.x,fmaf(w1.x,v2.x,fmaf(w2.x,v3.x,a1.x)));
                a1.y = fmaf(w0.y,v1.y,fmaf(w1.y,v2.y,fmaf(w2.y,v3.y,a1.y)));
                a1.z = fmaf(w0.z,v1.z,fmaf(w1.z,v2.z,fmaf(w2.z,v3.z,a1.z)));
                a1.w = fmaf(w0.w,v1.w,fmaf(w1.w,v2.w,fmaf(w2.w,v3.w,a1.w)));
            }
            y4p[(py * 8 + qx) * YP4 + c4]     = a0;
            y4p[(py * 8 + qx + 1) * YP4 + c4] = a1;
        }
        __syncthreads();

#pragma unroll 3
        for (int s = 0; s < C4; s += 2) {
            const int c4 = s + team;
            float4 y0 = y4p[(pq +  0) * YP4 + c4];
            float4 y1 = y4p[(pq + 16) * YP4 + c4];
            float4 y2 = y4p[(pq + 32) * YP4 + c4];
            float4 y3 = y4p[(pq + 48) * YP4 + c4];
#pragma unroll
            for (int k = 0; k < 4; k++) {
                float4 w = *(const float4*)&s_pw[(fb + k) * 100 + c4 * 4];
                acc[k*4+0] = fmaf(y0.x,w.x,fmaf(y0.y,w.y,fmaf(y0.z,w.z,fmaf(y0.w,w.w,acc[k*4+0]))));
                acc[k*4+1] = fmaf(y1.x,w.x,fmaf(y1.y,w.y,fmaf(y1.z,w.z,fmaf(y1.w,w.w,acc[k*4+1]))));
                acc[k*4+2] = fmaf(y2.x,w.x,fmaf(y2.y,w.y,fmaf(y2.z,w.z,fmaf(y2.w,w.w,acc[k*4+2]))));
                acc[k*4+3] = fmaf(y3.x,w.x,fmaf(y3.y,w.y,fmaf(y3.z,w.z,fmaf(y3.w,w.w,acc[k*4+3]))));
            }
        }
    }
    __syncthreads();

    if (team == 1) {
#pragma unroll
        for (int i = 0; i < 16; i++) s_red[r * 16 + i] = acc[i];
    }
    __syncthreads();
    if (team == 0) {
#pragma unroll
        for (int k = 0; k < 4; k++) {
            const float bias = __ldg(&pw_b[g * GF + fb + k]);
#pragma unroll
            for (int i = 0; i < 4; i++) {
                int p = pq + 16 * i;
                s_out[p * OUTP + fb + k] = acc[k*4+i] + s_red[r*16 + k*4+i] + bias;
            }
        }
    }
    __syncthreads();

    for (int i = tid; i < 4096; i += 512) {
        int p = i >> 6, f = i & 63;
        int py = p >> 3, px = p & 7;
        out[((size_t)((b * HH + ty0 + py) * WW) + tx0 + px) * (GG * GF)
            + g * GF + f] = s_out[p * OUTP + f];
    }
}

// ---------------------------------------------------------------------------
extern "C" void kernel_launch(void* const* d_in, const int* in_sizes, int n_in,
                              void* d_out, int out_size)
{
    const float* x     = (const float*)d_in[0];
    const float* off_w = (const float*)d_in[1];
    const float* off_b = (const float*)d_in[2];
    const float* dw_w  = (const float*)d_in[3];
    const float* dw_b  = (const float*)d_in[4];
    const float* pw_w  = (const float*)d_in[5];
    const float* pw_b  = (const float*)d_in[6];
    float* out = (float*)d_out;

    cudaFuncSetAttribute(k_offsets, cudaFuncAttributeMaxDynamicSharedMemorySize,
                         OFF_SMEM_BYTES);
    cudaFuncSetAttribute(k_dwpw, cudaFuncAttributeMaxDynamicSharedMemorySize,
                         SM_BYTES);

    k_offsets<<<dim3(WW/32, HH/32, BB*GG), 256, OFF_SMEM_BYTES>>>(x, off_w, off_b);
    k_sample<<<dim3(NP / 8, GG), 256>>>(x);
    k_dwpw<<<dim3(WW / 8, HH / 8, BB * GG), 512, SM_BYTES>>>(
        dw_w, dw_b, pw_w, pw_b, out);
}

// round 8
// speedup vs baseline: 1.4374x; 1.0637x over previous
#include <cuda_runtime.h>
#include <cuda_bf16.h>
#include <cstdint>
#include <math.h>

// Problem constants
#define BB   8
#define HH   128
#define WW   128
#define CIN  64
#define GG   2
#define GCH  32      // channels per group
#define SCH  288     // K*K*GC
#define GF   64      // filters per group
#define NP   (BB*HH*WW)   // 131072 pixels

// Scratch
__device__ float g_samp[(size_t)GG * NP * SCH];   // sampled field   (302 MB)
__device__ float g_off [(size_t)GG * NP * 18];    // offsets         (19 MB)

// ---------------------------------------------------------------------------
// cp.async helpers
// ---------------------------------------------------------------------------
__device__ __forceinline__ void cpa16(float* s, const float* gsrc, bool v) {
    unsigned int sa = (unsigned int)__cvta_generic_to_shared(s);
    asm volatile("cp.async.cg.shared.global [%0], [%1], 16, %2;"
                 :: "r"(sa), "l"(gsrc), "r"(v ? 16u : 0u));
}
__device__ __forceinline__ void cpa4(float* s, const float* gsrc) {
    unsigned int sa = (unsigned int)__cvta_generic_to_shared(s);
    asm volatile("cp.async.ca.shared.global [%0], [%1], 4;"
                 :: "r"(sa), "l"(gsrc));
}
#define CPA_COMMIT() asm volatile("cp.async.commit_group;")
#define CPA_WAIT0()  asm volatile("cp.async.wait_group 0;")

// ===========================================================================
// Kernel 0: offset conv (3x3, 32 -> 18) per group.
// 32x16 pixel tile, 256 threads, 2 pixels per thread (rows py0, py0+8).
// x staged in 2 channel chunks of 16. 512 blocks.
// ===========================================================================
#define OHP_W 34
#define OHP_H 18
#define XTS   17                  // padded channel stride
#define XT_F  (OHP_H*OHP_W*XTS)   // 10404 floats
#define WS_F  5760                // 9*32*20
#define OFF_SMEM_BYTES ((XT_F + WS_F + 32) * 4)

__global__ __launch_bounds__(256) void k_offsets(
    const float* __restrict__ x,      // [B,H,W,64]
    const float* __restrict__ off_w,  // [G,3,3,32,18]
    const float* __restrict__ off_b)  // [G,18]
{
    extern __shared__ float sm0[];
    float* xt   = sm0;                 // [pos][c pad 17]
    float* ws   = sm0 + XT_F;          // [t][c][j pad 20]
    float* wb   = sm0 + XT_F + WS_F;
    float* soff = sm0;                 // alias (xt dead after FMA loop)

    const int tid = threadIdx.x;
    const int z   = blockIdx.z;
    const int g   = z & 1;
    const int b   = z >> 1;
    const int ty0 = blockIdx.y * 16;
    const int tx0 = blockIdx.x * 32;

    for (int i = tid; i < WS_F; i += 256) {
        int r = i / 20, j = i % 20;
        ws[i] = (j < 18) ? off_w[(size_t)(g * 288 + r) * 18 + j] : 0.f;
    }
    if (tid < 18) wb[tid] = off_b[g * 18 + tid];

    const int px  = tid & 31;
    const int py0 = tid >> 5;          // rows py0 and py0+8

    float acc[2][18];
#pragma unroll
    for (int pp = 0; pp < 2; pp++)
#pragma unroll
        for (int j = 0; j < 18; j++) acc[pp][j] = 0.f;

    for (int cch = 0; cch < 2; cch++) {
        __syncthreads();
        for (int i = tid; i < OHP_H * OHP_W * 16; i += 256) {
            int pos = i >> 4, c = i & 15;
            int hy = ty0 + pos / OHP_W - 1, hx = tx0 + pos % OHP_W - 1;
            float v = 0.f;
            if (hy >= 0 && hy < HH && hx >= 0 && hx < WW)
                v = x[((size_t)((b * HH + hy) * WW + hx)) * CIN
                      + g * GCH + cch * 16 + c];
            xt[pos * XTS + c] = v;
        }
        __syncthreads();

#pragma unroll 1
        for (int t = 0; t < 9; t++) {
            const int dy = t / 3, dx = t % 3;
            const float* wt = &ws[(t * 32 + cch * 16) * 20];
            const int base = (dy * OHP_W + px + dx) * XTS;
#pragma unroll 2
            for (int c = 0; c < 16; c++) {
                float v0 = xt[base + ((py0    ) * OHP_W) * XTS + c];
                float v1 = xt[base + ((py0 + 8) * OHP_W) * XTS + c];
                const float4* wv = (const float4*)&wt[c * 20];
                float4 w0 = wv[0], w1 = wv[1], w2 = wv[2], w3 = wv[3];
                float2 w4 = *(const float2*)&wt[c * 20 + 16];
#pragma unroll
                for (int pp = 0; pp < 2; pp++) {
                    float v = pp == 0 ? v0 : v1;
                    acc[pp][ 0] = fmaf(v, w0.x, acc[pp][ 0]);
                    acc[pp][ 1] = fmaf(v, w0.y, acc[pp][ 1]);
                    acc[pp][ 2] = fmaf(v, w0.z, acc[pp][ 2]);
                    acc[pp][ 3] = fmaf(v, w0.w, acc[pp][ 3]);
                    acc[pp][ 4] = fmaf(v, w1.x, acc[pp][ 4]);
                    acc[pp][ 5] = fmaf(v, w1.y, acc[pp][ 5]);
                    acc[pp][ 6] = fmaf(v, w1.z, acc[pp][ 6]);
                    acc[pp][ 7] = fmaf(v, w1.w, acc[pp][ 7]);
                    acc[pp][ 8] = fmaf(v, w2.x, acc[pp][ 8]);
                    acc[pp][ 9] = fmaf(v, w2.y, acc[pp][ 9]);
                    acc[pp][10] = fmaf(v, w2.z, acc[pp][10]);
                    acc[pp][11] = fmaf(v, w2.w, acc[pp][11]);
                    acc[pp][12] = fmaf(v, w3.x, acc[pp][12]);
                    acc[pp][13] = fmaf(v, w3.y, acc[pp][13]);
                    acc[pp][14] = fmaf(v, w3.z, acc[pp][14]);
                    acc[pp][15] = fmaf(v, w3.w, acc[pp][15]);
                    acc[pp][16] = fmaf(v, w4.x, acc[pp][16]);
                    acc[pp][17] = fmaf(v, w4.y, acc[pp][17]);
                }
            }
        }
    }
    __syncthreads();   // xt reads done; safe to overwrite with soff

#pragma unroll
    for (int pp = 0; pp < 2; pp++) {
        const int p = (py0 + pp * 8) * 32 + px;
#pragma unroll
        for (int j = 0; j < 18; j++)
            soff[p * 18 + j] = acc[pp][j] + wb[j];
    }
    __syncthreads();

    const size_t pbase = (size_t)b * (HH * WW) + (size_t)ty0 * WW + tx0;
    for (int i = tid; i < 32 * 16 * 18; i += 256) {
        int row = i / 576, rem = i % 576;
        g_off[((size_t)g * NP + pbase + (size_t)row * WW) * 18 + rem] = soff[i];
    }
}

// ===========================================================================
// Kernel 1: bilinear sampling. One warp per (pixel, group). lane = channel.
// Taps processed in groups of 3: addresses+weights precomputed, then 12
// independent gathers in flight (MLP 12).
// ===========================================================================
__global__ __launch_bounds__(256) void k_sample(
    const float* __restrict__ x)      // [B,H,W,64]
{
    const int tid  = threadIdx.x;
    const int g    = blockIdx.y;
    const int warp = tid >> 5, lane = tid & 31;
    const int p   = blockIdx.x * 8 + warp;
    const int b   = p >> 14;
    const int rem = p & 16383;
    const int yy  = rem >> 7;
    const int xx  = rem & 127;

    float offv = 0.f;
    if (lane < 18) offv = g_off[((size_t)g * NP + p) * 18 + lane];

    const float* xg = x + (size_t)b * (HH * WW) * CIN + g * GCH + lane;
    float* outp = &g_samp[((size_t)g * NP + p) * SCH + lane];

#pragma unroll
    for (int grp = 0; grp < 3; grp++) {
        float wa[3], wb_[3], wc[3], wd[3];
        int oa[3], ob[3], oc[3], od[3];
#pragma unroll
        for (int j = 0; j < 3; j++) {
            const int k = grp * 3 + j;
            float ox = __shfl_sync(0xffffffffu, offv, 2 * k);
            float oy = __shfl_sync(0xffffffffu, offv, 2 * k + 1);
            float lx = (float)xx + (float)(k % 3 - 1) + ox;
            float ly = (float)yy + (float)(k / 3 - 1) + oy;
            lx = fminf(fmaxf(lx, 0.f), 127.f);
            ly = fminf(fmaxf(ly, 0.f), 127.f);
            float x0f = fminf(fmaxf(floorf(lx), 0.f), 127.f);
            float y0f = fminf(fmaxf(floorf(ly), 0.f), 127.f);
            float x1f = fminf(x0f + 1.f, 127.f);
            float y1f = fminf(y0f + 1.f, 127.f);
            int x0 = (int)x0f, x1 = (int)x1f, y0 = (int)y0f, y1 = (int)y1f;
            float dx1 = x1f - lx, dx0 = lx - x0f;
            float dy1 = y1f - ly, dy0 = ly - y0f;
            oa[j] = (y0 * WW + x0) * CIN;
            ob[j] = (y1 * WW + x0) * CIN;
            oc[j] = (y0 * WW + x1) * CIN;
            od[j] = (y1 * WW + x1) * CIN;
            wa[j]  = dx1 * dy1;  wb_[j] = dx1 * dy0;
            wc[j]  = dx0 * dy1;  wd[j]  = dx0 * dy0;
        }
        float va[3], vb[3], vc[3], vd[3];
#pragma unroll
        for (int j = 0; j < 3; j++) {
            va[j] = __ldg(xg + oa[j]);
            vb[j] = __ldg(xg + ob[j]);
            vc[j] = __ldg(xg + oc[j]);
            vd[j] = __ldg(xg + od[j]);
        }
#pragma unroll
        for (int j = 0; j < 3; j++)
            outp[(grp * 3 + j) * 32] =
                wa[j]*va[j] + wb_[j]*vb[j] + wc[j]*vc[j] + wd[j]*vd[j];
    }
}

// ===========================================================================
// Kernel 2: fused depthwise(3x3, groups=288) + pointwise(288->64).
// 8x8 tile per (b,g), 512 threads, 3 channel chunks of 96.
// cp.async: halo(cc+1) prefetched during pw(cc) -- staging latency hidden.
// ===========================================================================
#define CHUNK  96
#define C4     24                 // float4 per pixel per chunk
#define YP4    25                 // y row pad (float4)
#define SM_HALO (100 * CHUNK)     // 9600 floats
#define SM_Y    (64 * YP4 * 4)    // 6400 floats
#define SM_PW   (64 * 100)        // 6400 floats [f][c pad 100]
#define SM_DW   (9 * CHUNK)       // 864 floats
#define SM_BYTES ((SM_HALO + SM_Y + SM_PW + SM_DW) * 4)
#define OUTP    68

__global__ __launch_bounds__(512, 2) void k_dwpw(
    const float* __restrict__ dw_w,   // [G,3,3,288,1]
    const float* __restrict__ dw_b,   // [G,288]
    const float* __restrict__ pw_w,   // [G,1,1,288,64]
    const float* __restrict__ pw_b,   // [G,64]
    float* __restrict__ out)          // [B,H,W,128]
{
    extern __shared__ float smem[];
    float* s_halo = smem;
    float* s_y    = smem + SM_HALO;
    float* s_pw   = smem + SM_HALO + SM_Y;
    float* s_dw   = smem + SM_HALO + SM_Y + SM_PW;
    float* s_red  = s_pw;                 // post-loop aliases
    float* s_out  = s_halo;

    const int tid = threadIdx.x;
    const int z   = blockIdx.z;
    const int g   = z & 1;
    const int b   = z >> 1;
    const int ty0 = blockIdx.y * 8;
    const int tx0 = blockIdx.x * 8;

    const int team = tid >> 8;
    const int r    = tid & 255;
    const int fb   = (r >> 4) * 4;
    const int pq   = r & 15;

    float acc[16];
#pragma unroll
    for (int i = 0; i < 16; i++) acc[i] = 0.f;

    float4* t4  = (float4*)s_halo;
    float4* y4p = (float4*)s_y;
    float4* d4  = (float4*)s_dw;

    // async halo staging: 100 px x 24 float4, zero-fill OOB via src-size 0
    auto stage_halo = [&](int cc) {
        const int cbase = cc * CHUNK;
        for (int i = tid; i < 100 * C4; i += 512) {
            int hp = i / C4, c4 = i % C4;
            int hy = ty0 + hp / 10 - 1, hx = tx0 + hp % 10 - 1;
            bool ok = (hy >= 0 && hy < HH && hx >= 0 && hx < WW);
            const float* src = ok
                ? &g_samp[((size_t)g * NP +
                           (size_t)((b * HH + hy) * WW + hx)) * SCH + cbase + c4 * 4]
                : (const float*)g_samp;
            cpa16(&s_halo[i * 4], src, ok);
        }
    };

    // prologue: prefetch chunk 0's halo
    stage_halo(0);
    CPA_COMMIT();

    for (int cc = 0; cc < 3; cc++) {
        const int cbase = cc * CHUNK;
        __syncthreads();   // prev chunk's pw/dw consumers done before restaging

        // stage dw + pw weights for this chunk (async, small)
        for (int i = tid; i < 9 * C4; i += 512) {
            int t = i / C4, c4 = i % C4;
            cpa16(&s_dw[i * 4],
                  &dw_w[(size_t)g * 2592 + t * SCH + cbase + c4 * 4], true);
        }
        for (int i = tid; i < CHUNK * 64; i += 512) {
            int c = i >> 6, f = i & 63;
            cpa4(&s_pw[f * 100 + c],
                 &pw_w[(size_t)g * (SCH * GF) + (size_t)(cbase + c) * 64 + f]);
        }
        CPA_COMMIT();
        CPA_WAIT0();       // halo(cc) + weights(cc) complete
        __syncthreads();

        // --- depthwise 3x3: 2x1 pixel-pair register blocking ---
        for (int i = tid; i < 768; i += 512) {
            int c4 = i % C4;
            int pair = i / C4;
            int py = pair >> 2, qx = (pair & 3) * 2;
            float4 bias = __ldg((const float4*)&dw_b[g * SCH + cbase + c4 * 4]);
            float4 a0 = bias, a1 = bias;
#pragma unroll
            for (int ty = 0; ty < 3; ty++) {
                const float4* vr = &t4[((py + ty) * 10 + qx) * C4 + c4];
                float4 v0 = vr[0], v1 = vr[C4], v2 = vr[2*C4], v3 = vr[3*C4];
                float4 w0 = d4[(ty*3+0)*C4 + c4];
                float4 w1 = d4[(ty*3+1)*C4 + c4];
                float4 w2 = d4[(ty*3+2)*C4 + c4];
                a0.x = fmaf(w0.x,v0.x,fmaf(w1.x,v1.x,fmaf(w2.x,v2.x,a0.x)));
                a0.y = fmaf(w0.y,v0.y,fmaf(w1.y,v1.y,fmaf(w2.y,v2.y,a0.y)));
                a0.z = fmaf(w0.z,v0.z,fmaf(w1.z,v1.z,fmaf(w2.z,v2.z,a0.z)));
                a0.w = fmaf(w0.w,v0.w,fmaf(w1.w,v1.w,fmaf(w2.w,v2.w,a0.w)));
                a1.x = fmaf(w0.x,v1.x,fmaf(w1.x,v2.x,fmaf(w2.x,v3.x,a1.x)));
                a1.y = fmaf(w0.y,v1.y,fmaf(w1.y,v2.y,fmaf(w2.y,v3.y,a1.y)));
                a1.z = fmaf(w0.z,v1.z,fmaf(w1.z,v2.z,fmaf(w2.z,v3.z,a1.z)));
                a1.w = fmaf(w0.w,v1.w,fmaf(w1.w,v2.w,fmaf(w2.w,v3.w,a1.w)));
            }
            y4p[(py * 8 + qx) * YP4 + c4]     = a0;
            y4p[(py * 8 + qx + 1) * YP4 + c4] = a1;
        }
        __syncthreads();   // y ready; halo now dead

        // prefetch next chunk's halo into the (dead) halo buffer,
        // overlapped with the pw phase below
        if (cc < 2) {
            stage_halo(cc + 1);
            CPA_COMMIT();
        }

        // --- pointwise accumulate: this team's c4 slice ---
#pragma unroll 3
        for (int s = 0; s < C4; s += 2) {
            const int c4 = s + team;
            float4 y0 = y4p[(pq +  0) * YP4 + c4];
            float4 y1 = y4p[(pq + 16) * YP4 + c4];
            float4 y2 = y4p[(pq + 32) * YP4 + c4];
            float4 y3 = y4p[(pq + 48) * YP4 + c4];
#pragma unroll
            for (int k = 0; k < 4; k++) {
                float4 w = *(const float4*)&s_pw[(fb + k) * 100 + c4 * 4];
                acc[k*4+0] = fmaf(y0.x,w.x,fmaf(y0.y,w.y,fmaf(y0.z,w.z,fmaf(y0.w,w.w,acc[k*4+0]))));
                acc[k*4+1] = fmaf(y1.x,w.x,fmaf(y1.y,w.y,fmaf(y1.z,w.z,fmaf(y1.w,w.w,acc[k*4+1]))));
                acc[k*4+2] = fmaf(y2.x,w.x,fmaf(y2.y,w.y,fmaf(y2.z,w.z,fmaf(y2.w,w.w,acc[k*4+2]))));
                acc[k*4+3] = fmaf(y3.x,w.x,fmaf(y3.y,w.y,fmaf(y3.z,w.z,fmaf(y3.w,w.w,acc[k*4+3]))));
            }
        }
    }
    __syncthreads();

    if (team == 1) {
#pragma unroll
        for (int i = 0; i < 16; i++) s_red[r * 16 + i] = acc[i];
    }
    __syncthreads();
    if (team == 0) {
#pragma unroll
        for (int k = 0; k < 4; k++) {
            const float bias = __ldg(&pw_b[g * GF + fb + k]);
#pragma unroll
            for (int i = 0; i < 4; i++) {
                int p = pq + 16 * i;
                s_out[p * OUTP + fb + k] = acc[k*4+i] + s_red[r*16 + k*4+i] + bias;
            }
        }
    }
    __syncthreads();

    for (int i = tid; i < 4096; i += 512) {
        int p = i >> 6, f = i & 63;
        int py = p >> 3, px = p & 7;
        out[((size_t)((b * HH + ty0 + py) * WW) + tx0 + px) * (GG * GF)
            + g * GF + f] = s_out[p * OUTP + f];
    }
}

// ---------------------------------------------------------------------------
extern "C" void kernel_launch(void* const* d_in, const int* in_sizes, int n_in,
                              void* d_out, int out_size)
{
    const float* x     = (const float*)d_in[0];
    const float* off_w = (const float*)d_in[1];
    const float* off_b = (const float*)d_in[2];
    const float* dw_w  = (const float*)d_in[3];
    const float* dw_b  = (const float*)d_in[4];
    const float* pw_w  = (const float*)d_in[5];
    const float* pw_b  = (const float*)d_in[6];
    float* out = (float*)d_out;

    cudaFuncSetAttribute(k_offsets, cudaFuncAttributeMaxDynamicSharedMemorySize,
                         OFF_SMEM_BYTES);
    cudaFuncSetAttribute(k_dwpw, cudaFuncAttributeMaxDynamicSharedMemorySize,
                         SM_BYTES);

    k_offsets<<<dim3(WW/32, HH/16, BB*GG), 256, OFF_SMEM_BYTES>>>(x, off_w, off_b);
    k_sample<<<dim3(NP / 8, GG), 256>>>(x);
    k_dwpw<<<dim3(WW / 8, HH / 8, BB * GG), 512, SM_BYTES>>>(
        dw_w, dw_b, pw_w, pw_b, out);
}

// round 9
// speedup vs baseline: 1.8081x; 1.2578x over previous
#include <cuda_runtime.h>
#include <cuda_bf16.h>
#include <cstdint>
#include <math.h>

// Problem constants
#define BB   8
#define HH   128
#define WW   128
#define CIN  64
#define GG   2
#define GCH  32      // channels per group
#define SCH  288     // K*K*GC
#define GF   64      // filters per group
#define NP   (BB*HH*WW)   // 131072 pixels

// Scratch
__device__ float g_samp[(size_t)GG * NP * SCH];   // sampled field   (302 MB)
__device__ float g_off [(size_t)GG * NP * 18];    // offsets         (19 MB)
__device__ float g_pww [(size_t)GG * SCH * GF];   // tf32-rounded pw weights

// ---------------------------------------------------------------------------
// helpers
// ---------------------------------------------------------------------------
__device__ __forceinline__ void cpa16(float* s, const float* gsrc, bool v) {
    unsigned int sa = (unsigned int)__cvta_generic_to_shared(s);
    asm volatile("cp.async.cg.shared.global [%0], [%1], 16, %2;"
                 :: "r"(sa), "l"(gsrc), "r"(v ? 16u : 0u));
}
#define CPA_COMMIT() asm volatile("cp.async.commit_group;")
#define CPA_WAIT0()  asm volatile("cp.async.wait_group 0;")

__device__ __forceinline__ float to_tf32(float x) {
    unsigned int u;
    asm("cvt.rna.tf32.f32 %0, %1;" : "=r"(u) : "f"(x));
    return __uint_as_float(u);
}

__device__ __forceinline__ void mma_tf32(float* d,
    unsigned int a0, unsigned int a1, unsigned int a2, unsigned int a3,
    unsigned int b0, unsigned int b1)
{
    asm volatile(
        "mma.sync.aligned.m16n8k8.row.col.f32.tf32.tf32.f32 "
        "{%0,%1,%2,%3}, {%4,%5,%6,%7}, {%8,%9}, {%0,%1,%2,%3};"
        : "+f"(d[0]), "+f"(d[1]), "+f"(d[2]), "+f"(d[3])
        : "r"(a0), "r"(a1), "r"(a2), "r"(a3), "r"(b0), "r"(b1));
}

// ===========================================================================
// Kernel P: pre-round pw weights to tf32 (once, tiny)
// ===========================================================================
__global__ void k_prep(const float* __restrict__ pw_w) {
    int i = blockIdx.x * 256 + threadIdx.x;
    if (i < GG * SCH * GF) g_pww[i] = to_tf32(pw_w[i]);
}

// ===========================================================================
// Kernel 0: offset conv (3x3, 32 -> 18) per group. (frozen from round 8)
// ===========================================================================
#define OHP_W 34
#define OHP_H 18
#define XTS   17
#define XT_F  (OHP_H*OHP_W*XTS)
#define WS_F  5760
#define OFF_SMEM_BYTES ((XT_F + WS_F + 32) * 4)

__global__ __launch_bounds__(256) void k_offsets(
    const float* __restrict__ x,
    const float* __restrict__ off_w,
    const float* __restrict__ off_b)
{
    extern __shared__ float sm0[];
    float* xt   = sm0;
    float* ws   = sm0 + XT_F;
    float* wb   = sm0 + XT_F + WS_F;
    float* soff = sm0;

    const int tid = threadIdx.x;
    const int z   = blockIdx.z;
    const int g   = z & 1;
    const int b   = z >> 1;
    const int ty0 = blockIdx.y * 16;
    const int tx0 = blockIdx.x * 32;

    for (int i = tid; i < WS_F; i += 256) {
        int r = i / 20, j = i % 20;
        ws[i] = (j < 18) ? off_w[(size_t)(g * 288 + r) * 18 + j] : 0.f;
    }
    if (tid < 18) wb[tid] = off_b[g * 18 + tid];

    const int px  = tid & 31;
    const int py0 = tid >> 5;

    float acc[2][18];
#pragma unroll
    for (int pp = 0; pp < 2; pp++)
#pragma unroll
        for (int j = 0; j < 18; j++) acc[pp][j] = 0.f;

    for (int cch = 0; cch < 2; cch++) {
        __syncthreads();
        for (int i = tid; i < OHP_H * OHP_W * 16; i += 256) {
            int pos = i >> 4, c = i & 15;
            int hy = ty0 + pos / OHP_W - 1, hx = tx0 + pos % OHP_W - 1;
            float v = 0.f;
            if (hy >= 0 && hy < HH && hx >= 0 && hx < WW)
                v = x[((size_t)((b * HH + hy) * WW + hx)) * CIN
                      + g * GCH + cch * 16 + c];
            xt[pos * XTS + c] = v;
        }
        __syncthreads();

#pragma unroll 1
        for (int t = 0; t < 9; t++) {
            const int dy = t / 3, dx = t % 3;
            const float* wt = &ws[(t * 32 + cch * 16) * 20];
            const int base = (dy * OHP_W + px + dx) * XTS;
#pragma unroll 2
            for (int c = 0; c < 16; c++) {
                float v0 = xt[base + ((py0    ) * OHP_W) * XTS + c];
                float v1 = xt[base + ((py0 + 8) * OHP_W) * XTS + c];
                const float4* wv = (const float4*)&wt[c * 20];
                float4 w0 = wv[0], w1 = wv[1], w2 = wv[2], w3 = wv[3];
                float2 w4 = *(const float2*)&wt[c * 20 + 16];
#pragma unroll
                for (int pp = 0; pp < 2; pp++) {
                    float v = pp == 0 ? v0 : v1;
                    acc[pp][ 0] = fmaf(v, w0.x, acc[pp][ 0]);
                    acc[pp][ 1] = fmaf(v, w0.y, acc[pp][ 1]);
                    acc[pp][ 2] = fmaf(v, w0.z, acc[pp][ 2]);
                    acc[pp][ 3] = fmaf(v, w0.w, acc[pp][ 3]);
                    acc[pp][ 4] = fmaf(v, w1.x, acc[pp][ 4]);
                    acc[pp][ 5] = fmaf(v, w1.y, acc[pp][ 5]);
                    acc[pp][ 6] = fmaf(v, w1.z, acc[pp][ 6]);
                    acc[pp][ 7] = fmaf(v, w1.w, acc[pp][ 7]);
                    acc[pp][ 8] = fmaf(v, w2.x, acc[pp][ 8]);
                    acc[pp][ 9] = fmaf(v, w2.y, acc[pp][ 9]);
                    acc[pp][10] = fmaf(v, w2.z, acc[pp][10]);
                    acc[pp][11] = fmaf(v, w2.w, acc[pp][11]);
                    acc[pp][12] = fmaf(v, w3.x, acc[pp][12]);
                    acc[pp][13] = fmaf(v, w3.y, acc[pp][13]);
                    acc[pp][14] = fmaf(v, w3.z, acc[pp][14]);
                    acc[pp][15] = fmaf(v, w3.w, acc[pp][15]);
                    acc[pp][16] = fmaf(v, w4.x, acc[pp][16]);
                    acc[pp][17] = fmaf(v, w4.y, acc[pp][17]);
                }
            }
        }
    }
    __syncthreads();

#pragma unroll
    for (int pp = 0; pp < 2; pp++) {
        const int p = (py0 + pp * 8) * 32 + px;
#pragma unroll
        for (int j = 0; j < 18; j++)
            soff[p * 18 + j] = acc[pp][j] + wb[j];
    }
    __syncthreads();

    const size_t pbase = (size_t)b * (HH * WW) + (size_t)ty0 * WW + tx0;
    for (int i = tid; i < 32 * 16 * 18; i += 256) {
        int row = i / 576, rem = i % 576;
        g_off[((size_t)g * NP + pbase + (size_t)row * WW) * 18 + rem] = soff[i];
    }
}

// ===========================================================================
// Kernel 1: bilinear sampling (frozen from round 8; MLP-12 tap batching)
// ===========================================================================
__global__ __launch_bounds__(256) void k_sample(
    const float* __restrict__ x)
{
    const int tid  = threadIdx.x;
    const int g    = blockIdx.y;
    const int warp = tid >> 5, lane = tid & 31;
    const int p   = blockIdx.x * 8 + warp;
    const int b   = p >> 14;
    const int rem = p & 16383;
    const int yy  = rem >> 7;
    const int xx  = rem & 127;

    float offv = 0.f;
    if (lane < 18) offv = g_off[((size_t)g * NP + p) * 18 + lane];

    const float* xg = x + (size_t)b * (HH * WW) * CIN + g * GCH + lane;
    float* outp = &g_samp[((size_t)g * NP + p) * SCH + lane];

#pragma unroll
    for (int grp = 0; grp < 3; grp++) {
        float wa[3], wb_[3], wc[3], wd[3];
        int oa[3], ob[3], oc[3], od[3];
#pragma unroll
        for (int j = 0; j < 3; j++) {
            const int k = grp * 3 + j;
            float ox = __shfl_sync(0xffffffffu, offv, 2 * k);
            float oy = __shfl_sync(0xffffffffu, offv, 2 * k + 1);
            float lx = (float)xx + (float)(k % 3 - 1) + ox;
            float ly = (float)yy + (float)(k / 3 - 1) + oy;
            lx = fminf(fmaxf(lx, 0.f), 127.f);
            ly = fminf(fmaxf(ly, 0.f), 127.f);
            float x0f = fminf(fmaxf(floorf(lx), 0.f), 127.f);
            float y0f = fminf(fmaxf(floorf(ly), 0.f), 127.f);
            float x1f = fminf(x0f + 1.f, 127.f);
            float y1f = fminf(y0f + 1.f, 127.f);
            int x0 = (int)x0f, x1 = (int)x1f, y0 = (int)y0f, y1 = (int)y1f;
            float dx1 = x1f - lx, dx0 = lx - x0f;
            float dy1 = y1f - ly, dy0 = ly - y0f;
            oa[j] = (y0 * WW + x0) * CIN;
            ob[j] = (y1 * WW + x0) * CIN;
            oc[j] = (y0 * WW + x1) * CIN;
            od[j] = (y1 * WW + x1) * CIN;
            wa[j]  = dx1 * dy1;  wb_[j] = dx1 * dy0;
            wc[j]  = dx0 * dy1;  wd[j]  = dx0 * dy0;
        }
        float va[3], vb[3], vc[3], vd[3];
#pragma unroll
        for (int j = 0; j < 3; j++) {
            va[j] = __ldg(xg + oa[j]);
            vb[j] = __ldg(xg + ob[j]);
            vc[j] = __ldg(xg + oc[j]);
            vd[j] = __ldg(xg + od[j]);
        }
#pragma unroll
        for (int j = 0; j < 3; j++)
            outp[(grp * 3 + j) * 32] =
                wa[j]*va[j] + wb_[j]*vb[j] + wc[j]*vc[j] + wd[j]*vd[j];
    }
}

// ===========================================================================
// Kernel 2: fused depthwise(3x3) + pointwise(288->64) with tf32 tensor cores.
// 8x8 tile per (b,g), 512 threads, 3 channel chunks of 96.
// dw: FFMA as before (y rounded to tf32 on store).
// pw: mma.m16n8k8.tf32 -- 16 warps = 2 K-teams x (4 m-tiles x 2 n-tiles n32).
//   s_y  [64 px][100]  (stride 100 -> conflict-free A frags)
//   s_pw [96 ch][72]   (stride 72  -> conflict-free B frags)
// ===========================================================================
#define CHUNK  96
#define C4     24
#define SM_HALO (100 * CHUNK)     // 9600 floats
#define SM_Y    (64 * 100)        // 6400 floats
#define SM_PW   (96 * 72)         // 6912 floats
#define SM_DW   (9 * CHUNK)       // 864 floats
#define SM_BYTES ((SM_HALO + SM_Y + SM_PW + SM_DW) * 4)
#define OUTP    68

__global__ __launch_bounds__(512, 2) void k_dwpw(
    const float* __restrict__ dw_w,   // [G,3,3,288,1]
    const float* __restrict__ dw_b,   // [G,288]
    const float* __restrict__ pw_b,   // [G,64]
    float* __restrict__ out)          // [B,H,W,128]
{
    extern __shared__ float smem[];
    float* s_halo = smem;
    float* s_y    = smem + SM_HALO;
    float* s_pw   = smem + SM_HALO + SM_Y;
    float* s_dw   = smem + SM_HALO + SM_Y + SM_PW;
    float* s_red  = s_pw;                 // post-loop aliases
    float* s_out  = s_halo;

    const int tid = threadIdx.x;
    const int z   = blockIdx.z;
    const int gg  = z & 1;
    const int b   = z >> 1;
    const int ty0 = blockIdx.y * 8;
    const int tx0 = blockIdx.x * 8;

    const int warp = tid >> 5, lane = tid & 31;
    const int lg   = lane >> 2;            // groupID (0..7)
    const int lt   = lane & 3;             // threadID in group (0..3)
    const int team = warp >> 3;            // K split
    const int mtb  = (warp & 3) * 16;      // m tile base (px)
    const int ntb  = ((warp >> 2) & 1) * 32;  // n tile base (filter)

    float acc[4][4];
#pragma unroll
    for (int j = 0; j < 4; j++)
#pragma unroll
        for (int q = 0; q < 4; q++) acc[j][q] = 0.f;

    float4* t4 = (float4*)s_halo;
    float4* d4 = (float4*)s_dw;

    auto stage_halo = [&](int cc) {
        const int cbase = cc * CHUNK;
        for (int i = tid; i < 100 * C4; i += 512) {
            int hp = i / C4, c4 = i % C4;
            int hy = ty0 + hp / 10 - 1, hx = tx0 + hp % 10 - 1;
            bool ok = (hy >= 0 && hy < HH && hx >= 0 && hx < WW);
            const float* src = ok
                ? &g_samp[((size_t)gg * NP +
                           (size_t)((b * HH + hy) * WW + hx)) * SCH + cbase + c4 * 4]
                : (const float*)g_samp;
            cpa16(&s_halo[i * 4], src, ok);
        }
    };

    stage_halo(0);
    CPA_COMMIT();

    for (int cc = 0; cc < 3; cc++) {
        const int cbase = cc * CHUNK;
        __syncthreads();   // prev chunk's pw consumers done before restaging

        // stage dw weights + pre-rounded pw weights (async)
        for (int i = tid; i < 9 * C4; i += 512) {
            int t = i / C4, c4 = i % C4;
            cpa16(&s_dw[i * 4],
                  &dw_w[(size_t)gg * 2592 + t * SCH + cbase + c4 * 4], true);
        }
        for (int i = tid; i < 96 * 16; i += 512) {
            int c = i >> 4, f4 = i & 15;
            cpa16(&s_pw[c * 72 + f4 * 4],
                  &g_pww[((size_t)gg * SCH + cbase + c) * 64 + f4 * 4], true);
        }
        CPA_COMMIT();
        CPA_WAIT0();
        __syncthreads();

        // --- depthwise 3x3, y rounded to tf32 on store ---
        for (int i = tid; i < 768; i += 512) {
            int c4 = i % C4;
            int pair = i / C4;
            int py = pair >> 2, qx = (pair & 3) * 2;
            float4 bias = __ldg((const float4*)&dw_b[gg * SCH + cbase + c4 * 4]);
            float4 a0 = bias, a1 = bias;
#pragma unroll
            for (int ty = 0; ty < 3; ty++) {
                const float4* vr = &t4[((py + ty) * 10 + qx) * C4 + c4];
                float4 v0 = vr[0], v1 = vr[C4], v2 = vr[2*C4], v3 = vr[3*C4];
                float4 w0 = d4[(ty*3+0)*C4 + c4];
                float4 w1 = d4[(ty*3+1)*C4 + c4];
                float4 w2 = d4[(ty*3+2)*C4 + c4];
                a0.x = fmaf(w0.x,v0.x,fmaf(w1.x,v1.x,fmaf(w2.x,v2.x,a0.x)));
                a0.y = fmaf(w0.y,v0.y,fmaf(w1.y,v1.y,fmaf(w2.y,v2.y,a0.y)));
                a0.z = fmaf(w0.z,v0.z,fmaf(w1.z,v1.z,fmaf(w2.z,v2.z,a0.z)));
                a0.w = fmaf(w0.w,v0.w,fmaf(w1.w,v1.w,fmaf(w2.w,v2.w,a0.w)));
                a1.x = fmaf(w0.x,v1.x,fmaf(w1.x,v2.x,fmaf(w2.x,v3.x,a1.x)));
                a1.y = fmaf(w0.y,v1.y,fmaf(w1.y,v2.y,fmaf(w2.y,v3.y,a1.y)));
                a1.z = fmaf(w0.z,v1.z,fmaf(w1.z,v2.z,fmaf(w2.z,v3.z,a1.z)));
                a1.w = fmaf(w0.w,v1.w,fmaf(w1.w,v2.w,fmaf(w2.w,v3.w,a1.w)));
            }
            float4 r0 = make_float4(to_tf32(a0.x), to_tf32(a0.y),
                                    to_tf32(a0.z), to_tf32(a0.w));
            float4 r1 = make_float4(to_tf32(a1.x), to_tf32(a1.y),
                                    to_tf32(a1.z), to_tf32(a1.w));
            *(float4*)&s_y[(py * 8 + qx    ) * 100 + c4 * 4] = r0;
            *(float4*)&s_y[(py * 8 + qx + 1) * 100 + c4 * 4] = r1;
        }
        __syncthreads();   // y ready; halo dead

        if (cc < 2) {
            stage_halo(cc + 1);
            CPA_COMMIT();
        }

        // --- pointwise via tf32 mma: this team's 48-channel K slice ---
#pragma unroll
        for (int s = 0; s < 6; s++) {
            const int k0 = team * 48 + s * 8;
            const unsigned int* yA =
                (const unsigned int*)&s_y[(mtb + lg) * 100 + k0 + lt];
            unsigned int a0 = yA[0],   a1 = yA[800];
            unsigned int a2 = yA[4],   a3 = yA[804];
#pragma unroll
            for (int j = 0; j < 4; j++) {
                unsigned int b0 = *(const unsigned int*)
                    &s_pw[(k0 + lt    ) * 72 + ntb + j * 8 + lg];
                unsigned int b1 = *(const unsigned int*)
                    &s_pw[(k0 + lt + 4) * 72 + ntb + j * 8 + lg];
                mma_tf32(acc[j], a0, a1, a2, a3, b0, b1);
            }
        }
    }
    __syncthreads();

    // split-K reduce across teams
    if (team == 1) {
        float* dst = &s_red[((warp & 7) * 32 + lane) * 16];
#pragma unroll
        for (int j = 0; j < 4; j++)
#pragma unroll
            for (int q = 0; q < 4; q++) dst[j * 4 + q] = acc[j][q];
    }
    __syncthreads();
    if (team == 0) {
        const float* src = &s_red[((warp & 7) * 32 + lane) * 16];
        const int px0 = mtb + lg, px1 = mtb + lg + 8;
#pragma unroll
        for (int j = 0; j < 4; j++) {
            int f0 = ntb + j * 8 + 2 * lt;
            float b0v = __ldg(&pw_b[gg * GF + f0]);
            float b1v = __ldg(&pw_b[gg * GF + f0 + 1]);
            s_out[px0 * OUTP + f0]     = acc[j][0] + src[j*4+0] + b0v;
            s_out[px0 * OUTP + f0 + 1] = acc[j][1] + src[j*4+1] + b1v;
            s_out[px1 * OUTP + f0]     = acc[j][2] + src[j*4+2] + b0v;
            s_out[px1 * OUTP + f0 + 1] = acc[j][3] + src[j*4+3] + b1v;
        }
    }
    __syncthreads();

    for (int i = tid; i < 4096; i += 512) {
        int p = i >> 6, f = i & 63;
        int py = p >> 3, px = p & 7;
        out[((size_t)((b * HH + ty0 + py) * WW) + tx0 + px) * (GG * GF)
            + gg * GF + f] = s_out[p * OUTP + f];
    }
}

// ---------------------------------------------------------------------------
extern "C" void kernel_launch(void* const* d_in, const int* in_sizes, int n_in,
                              void* d_out, int out_size)
{
    const float* x     = (const float*)d_in[0];
    const float* off_w = (const float*)d_in[1];
    const float* off_b = (const float*)d_in[2];
    const float* dw_w  = (const float*)d_in[3];
    const float* dw_b  = (const float*)d_in[4];
    const float* pw_w  = (const float*)d_in[5];
    const float* pw_b  = (const float*)d_in[6];
    float* out = (float*)d_out;

    cudaFuncSetAttribute(k_offsets, cudaFuncAttributeMaxDynamicSharedMemorySize,
                         OFF_SMEM_BYTES);
    cudaFuncSetAttribute(k_dwpw, cudaFuncAttributeMaxDynamicSharedMemorySize,
                         SM_BYTES);

    k_prep<<<(GG * SCH * GF + 255) / 256, 256>>>(pw_w);
    k_offsets<<<dim3(WW/32, HH/16, BB*GG), 256, OFF_SMEM_BYTES>>>(x, off_w, off_b);
    k_sample<<<dim3(NP / 8, GG), 256>>>(x);
    k_dwpw<<<dim3(WW / 8, HH / 8, BB * GG), 512, SM_BYTES>>>(
        dw_w, dw_b, pw_b, out);
}

// round 10
// speedup vs baseline: 2.1636x; 1.1967x over previous
#include <cuda_runtime.h>
#include <cuda_fp16.h>
#include <cstdint>
#include <math.h>

// Problem constants
#define BB   8
#define HH   128
#define WW   128
#define CIN  64
#define GG   2
#define GCH  32      // channels per group
#define SCH  288     // K*K*GC
#define GF   64      // filters per group
#define NP   (BB*HH*WW)   // 131072 pixels

// Scratch
__device__ __half g_samp16[(size_t)GG * NP * SCH]; // sampled field (151 MB)
__device__ float  g_off [(size_t)GG * NP * 18];    // offsets       (19 MB)
__device__ float  g_pww [(size_t)GG * SCH * GF];   // tf32-rounded pw weights

// ---------------------------------------------------------------------------
// helpers
// ---------------------------------------------------------------------------
__device__ __forceinline__ void cpa16(void* s, const void* gsrc, bool v) {
    unsigned int sa = (unsigned int)__cvta_generic_to_shared(s);
    asm volatile("cp.async.cg.shared.global [%0], [%1], 16, %2;"
                 :: "r"(sa), "l"(gsrc), "r"(v ? 16u : 0u));
}
#define CPA_COMMIT() asm volatile("cp.async.commit_group;")
#define CPA_WAIT0()  asm volatile("cp.async.wait_group 0;")

__device__ __forceinline__ float to_tf32(float x) {
    unsigned int u;
    asm("cvt.rna.tf32.f32 %0, %1;" : "=r"(u) : "f"(x));
    return __uint_as_float(u);
}

__device__ __forceinline__ void mma_tf32(float* d,
    unsigned int a0, unsigned int a1, unsigned int a2, unsigned int a3,
    unsigned int b0, unsigned int b1)
{
    asm volatile(
        "mma.sync.aligned.m16n8k8.row.col.f32.tf32.tf32.f32 "
        "{%0,%1,%2,%3}, {%4,%5,%6,%7}, {%8,%9}, {%0,%1,%2,%3};"
        : "+f"(d[0]), "+f"(d[1]), "+f"(d[2]), "+f"(d[3])
        : "r"(a0), "r"(a1), "r"(a2), "r"(a3), "r"(b0), "r"(b1));
}

// ===========================================================================
// Kernel P: pre-round pw weights to tf32 (once, tiny)
// ===========================================================================
__global__ void k_prep(const float* __restrict__ pw_w) {
    int i = blockIdx.x * 256 + threadIdx.x;
    if (i < GG * SCH * GF) g_pww[i] = to_tf32(pw_w[i]);
}

// ===========================================================================
// Kernel 0: offset conv (3x3, 32 -> 18) per group. (frozen)
// ===========================================================================
#define OHP_W 34
#define OHP_H 18
#define XTS   17
#define XT_F  (OHP_H*OHP_W*XTS)
#define WS_F  5760
#define OFF_SMEM_BYTES ((XT_F + WS_F + 32) * 4)

__global__ __launch_bounds__(256) void k_offsets(
    const float* __restrict__ x,
    const float* __restrict__ off_w,
    const float* __restrict__ off_b)
{
    extern __shared__ float sm0[];
    float* xt   = sm0;
    float* ws   = sm0 + XT_F;
    float* wb   = sm0 + XT_F + WS_F;
    float* soff = sm0;

    const int tid = threadIdx.x;
    const int z   = blockIdx.z;
    const int g   = z & 1;
    const int b   = z >> 1;
    const int ty0 = blockIdx.y * 16;
    const int tx0 = blockIdx.x * 32;

    for (int i = tid; i < WS_F; i += 256) {
        int r = i / 20, j = i % 20;
        ws[i] = (j < 18) ? off_w[(size_t)(g * 288 + r) * 18 + j] : 0.f;
    }
    if (tid < 18) wb[tid] = off_b[g * 18 + tid];

    const int px  = tid & 31;
    const int py0 = tid >> 5;

    float acc[2][18];
#pragma unroll
    for (int pp = 0; pp < 2; pp++)
#pragma unroll
        for (int j = 0; j < 18; j++) acc[pp][j] = 0.f;

    for (int cch = 0; cch < 2; cch++) {
        __syncthreads();
        for (int i = tid; i < OHP_H * OHP_W * 16; i += 256) {
            int pos = i >> 4, c = i & 15;
            int hy = ty0 + pos / OHP_W - 1, hx = tx0 + pos % OHP_W - 1;
            float v = 0.f;
            if (hy >= 0 && hy < HH && hx >= 0 && hx < WW)
                v = x[((size_t)((b * HH + hy) * WW + hx)) * CIN
                      + g * GCH + cch * 16 + c];
            xt[pos * XTS + c] = v;
        }
        __syncthreads();

#pragma unroll 1
        for (int t = 0; t < 9; t++) {
            const int dy = t / 3, dx = t % 3;
            const float* wt = &ws[(t * 32 + cch * 16) * 20];
            const int base = (dy * OHP_W + px + dx) * XTS;
#pragma unroll 2
            for (int c = 0; c < 16; c++) {
                float v0 = xt[base + ((py0    ) * OHP_W) * XTS + c];
                float v1 = xt[base + ((py0 + 8) * OHP_W) * XTS + c];
                const float4* wv = (const float4*)&wt[c * 20];
                float4 w0 = wv[0], w1 = wv[1], w2 = wv[2], w3 = wv[3];
                float2 w4 = *(const float2*)&wt[c * 20 + 16];
#pragma unroll
                for (int pp = 0; pp < 2; pp++) {
                    float v = pp == 0 ? v0 : v1;
                    acc[pp][ 0] = fmaf(v, w0.x, acc[pp][ 0]);
                    acc[pp][ 1] = fmaf(v, w0.y, acc[pp][ 1]);
                    acc[pp][ 2] = fmaf(v, w0.z, acc[pp][ 2]);
                    acc[pp][ 3] = fmaf(v, w0.w, acc[pp][ 3]);
                    acc[pp][ 4] = fmaf(v, w1.x, acc[pp][ 4]);
                    acc[pp][ 5] = fmaf(v, w1.y, acc[pp][ 5]);
                    acc[pp][ 6] = fmaf(v, w1.z, acc[pp][ 6]);
                    acc[pp][ 7] = fmaf(v, w1.w, acc[pp][ 7]);
                    acc[pp][ 8] = fmaf(v, w2.x, acc[pp][ 8]);
                    acc[pp][ 9] = fmaf(v, w2.y, acc[pp][ 9]);
                    acc[pp][10] = fmaf(v, w2.z, acc[pp][10]);
                    acc[pp][11] = fmaf(v, w2.w, acc[pp][11]);
                    acc[pp][12] = fmaf(v, w3.x, acc[pp][12]);
                    acc[pp][13] = fmaf(v, w3.y, acc[pp][13]);
                    acc[pp][14] = fmaf(v, w3.z, acc[pp][14]);
                    acc[pp][15] = fmaf(v, w3.w, acc[pp][15]);
                    acc[pp][16] = fmaf(v, w4.x, acc[pp][16]);
                    acc[pp][17] = fmaf(v, w4.y, acc[pp][17]);
                }
            }
        }
    }
    __syncthreads();

#pragma unroll
    for (int pp = 0; pp < 2; pp++) {
        const int p = (py0 + pp * 8) * 32 + px;
#pragma unroll
        for (int j = 0; j < 18; j++)
            soff[p * 18 + j] = acc[pp][j] + wb[j];
    }
    __syncthreads();

    const size_t pbase = (size_t)b * (HH * WW) + (size_t)ty0 * WW + tx0;
    for (int i = tid; i < 32 * 16 * 18; i += 256) {
        int row = i / 576, rem = i % 576;
        g_off[((size_t)g * NP + pbase + (size_t)row * WW) * 18 + rem] = soff[i];
    }
}

// ===========================================================================
// Kernel 1: bilinear sampling (MLP-12 tap batching). fp16 output.
// ===========================================================================
__global__ __launch_bounds__(256) void k_sample(
    const float* __restrict__ x)
{
    const int tid  = threadIdx.x;
    const int g    = blockIdx.y;
    const int warp = tid >> 5, lane = tid & 31;
    const int p   = blockIdx.x * 8 + warp;
    const int b   = p >> 14;
    const int rem = p & 16383;
    const int yy  = rem >> 7;
    const int xx  = rem & 127;

    float offv = 0.f;
    if (lane < 18) offv = g_off[((size_t)g * NP + p) * 18 + lane];

    const float* xg = x + (size_t)b * (HH * WW) * CIN + g * GCH + lane;
    __half* outp = &g_samp16[((size_t)g * NP + p) * SCH + lane];

#pragma unroll
    for (int grp = 0; grp < 3; grp++) {
        float wa[3], wb_[3], wc[3], wd[3];
        int oa[3], ob[3], oc[3], od[3];
#pragma unroll
        for (int j = 0; j < 3; j++) {
            const int k = grp * 3 + j;
            float ox = __shfl_sync(0xffffffffu, offv, 2 * k);
            float oy = __shfl_sync(0xffffffffu, offv, 2 * k + 1);
            float lx = (float)xx + (float)(k % 3 - 1) + ox;
            float ly = (float)yy + (float)(k / 3 - 1) + oy;
            lx = fminf(fmaxf(lx, 0.f), 127.f);
            ly = fminf(fmaxf(ly, 0.f), 127.f);
            float x0f = fminf(fmaxf(floorf(lx), 0.f), 127.f);
            float y0f = fminf(fmaxf(floorf(ly), 0.f), 127.f);
            float x1f = fminf(x0f + 1.f, 127.f);
            float y1f = fminf(y0f + 1.f, 127.f);
            int x0 = (int)x0f, x1 = (int)x1f, y0 = (int)y0f, y1 = (int)y1f;
            float dx1 = x1f - lx, dx0 = lx - x0f;
            float dy1 = y1f - ly, dy0 = ly - y0f;
            oa[j] = (y0 * WW + x0) * CIN;
            ob[j] = (y1 * WW + x0) * CIN;
            oc[j] = (y0 * WW + x1) * CIN;
            od[j] = (y1 * WW + x1) * CIN;
            wa[j]  = dx1 * dy1;  wb_[j] = dx1 * dy0;
            wc[j]  = dx0 * dy1;  wd[j]  = dx0 * dy0;
        }
        float va[3], vb[3], vc[3], vd[3];
#pragma unroll
        for (int j = 0; j < 3; j++) {
            va[j] = __ldg(xg + oa[j]);
            vb[j] = __ldg(xg + ob[j]);
            vc[j] = __ldg(xg + oc[j]);
            vd[j] = __ldg(xg + od[j]);
        }
#pragma unroll
        for (int j = 0; j < 3; j++)
            outp[(grp * 3 + j) * 32] = __float2half_rn(
                wa[j]*va[j] + wb_[j]*vb[j] + wc[j]*vc[j] + wd[j]*vd[j]);
    }
}

// ===========================================================================
// Kernel 2: fused depthwise(3x3) + pointwise(288->64, tf32 mma).
// 8x8 tile per (b,g), 512 threads, 3 channel chunks of 96.
// halo in fp16 (half L1 bytes); base-pointer table kills staging ALU;
// dw: 4px x 4ch strip per thread; pw: validated m16n8k8 tf32 layout.
// ===========================================================================
#define CHUNK  96
#define SM_HALO_H (100 * CHUNK)       // halves: 9600 (19200 B)
#define SM_HALO_F (SM_HALO_H / 2)     // float-equivalents: 4800
#define SM_Y    (64 * 100)            // 6400 floats
#define SM_PW   (96 * 72)             // 6912 floats
#define SM_DW   (9 * CHUNK)           // 864 floats
#define SM_BASE 200                   // 100 pointers (800 B)
#define SM_BYTES ((SM_HALO_F + SM_Y + SM_PW + SM_DW + SM_BASE + 8) * 4)
#define OUTP    68

__global__ __launch_bounds__(512, 2) void k_dwpw(
    const float* __restrict__ dw_w,   // [G,3,3,288,1]
    const float* __restrict__ dw_b,   // [G,288]
    const float* __restrict__ pw_b,   // [G,64]
    float* __restrict__ out)          // [B,H,W,128]
{
    extern __shared__ float smem[];
    __half* s_hal = (__half*)smem;                     // fp16 halo
    float* s_y    = smem + SM_HALO_F;
    float* s_pw   = smem + SM_HALO_F + SM_Y;
    float* s_dw   = smem + SM_HALO_F + SM_Y + SM_PW;
    const __half** s_base =
        (const __half**)(smem + SM_HALO_F + SM_Y + SM_PW + SM_DW + 8);
    float* s_red  = s_pw;                 // post-loop aliases
    float* s_out  = smem;                 // 64*68 floats < halo region

    const int tid = threadIdx.x;
    const int z   = blockIdx.z;
    const int gg  = z & 1;
    const int b   = z >> 1;
    const int ty0 = blockIdx.y * 8;
    const int tx0 = blockIdx.x * 8;

    const int warp = tid >> 5, lane = tid & 31;
    const int lg   = lane >> 2;
    const int lt   = lane & 3;
    const int team = warp >> 3;
    const int mtb  = (warp & 3) * 16;
    const int ntb  = ((warp >> 2) & 1) * 32;

    float acc[4][4];
#pragma unroll
    for (int j = 0; j < 4; j++)
#pragma unroll
        for (int q = 0; q < 4; q++) acc[j][q] = 0.f;

    float4* d4 = (float4*)s_dw;

    // --- halo base-pointer table (once per block) ---
    if (tid < 100) {
        int hy = ty0 + tid / 10 - 1, hx = tx0 + tid % 10 - 1;
        bool ok = (hy >= 0 && hy < HH && hx >= 0 && hx < WW);
        s_base[tid] = ok
            ? &g_samp16[((size_t)gg * NP + (size_t)((b * HH + hy) * WW + hx)) * SCH]
            : (const __half*)0;
    }
    __syncthreads();

    // warp-structured halo staging: no div/mod, 12 cpa16 per pixel
    auto stage_halo = [&](int cc) {
        const int cbase = cc * CHUNK;
        if (lane < 12) {
            for (int hp = warp; hp < 100; hp += 16) {
                const __half* base = s_base[hp];
                bool ok = (base != 0);
                const void* src = ok ? (const void*)(base + cbase + lane * 8)
                                     : (const void*)g_samp16;
                cpa16(&s_hal[hp * CHUNK + lane * 8], src, ok);
            }
        }
    };

    stage_halo(0);
    CPA_COMMIT();

    for (int cc = 0; cc < 3; cc++) {
        const int cbase = cc * CHUNK;
        __syncthreads();   // prev chunk's pw consumers done before restaging

        // stage dw weights + pre-rounded pw weights (async)
        for (int i = tid; i < 9 * 24; i += 512) {
            int t = i / 24, c4 = i % 24;
            cpa16(&s_dw[i * 4],
                  &dw_w[(size_t)gg * 2592 + t * SCH + cbase + c4 * 4], true);
        }
        for (int i = tid; i < 96 * 16; i += 512) {
            int c = i >> 4, f4 = i & 15;
            cpa16(&s_pw[c * 72 + f4 * 4],
                  &g_pww[((size_t)gg * SCH + cbase + c) * 64 + f4 * 4], true);
        }
        CPA_COMMIT();
        CPA_WAIT0();
        __syncthreads();

        // --- depthwise 3x3: strip of 4 px x 4 ch per thread (384 active) ---
        if (tid < 384) {
            const int strip = tid / 24, c4 = tid % 24;
            const int py = strip >> 1, qx0 = (strip & 1) * 4;
            float4 bias = __ldg((const float4*)&dw_b[gg * SCH + cbase + c4 * 4]);
            float a[4][4];
#pragma unroll
            for (int oxp = 0; oxp < 4; oxp++) {
                a[oxp][0] = bias.x; a[oxp][1] = bias.y;
                a[oxp][2] = bias.z; a[oxp][3] = bias.w;
            }
#pragma unroll
            for (int ty = 0; ty < 3; ty++) {
                const __half* hrow = &s_hal[((py + ty) * 10 + qx0) * CHUNK + c4 * 4];
                float vv[6][4];
#pragma unroll
                for (int i = 0; i < 6; i++) {
                    __half2 h01 = *(const __half2*)&hrow[i * CHUNK];
                    __half2 h23 = *(const __half2*)&hrow[i * CHUNK + 2];
                    vv[i][0] = __low2float(h01);  vv[i][1] = __high2float(h01);
                    vv[i][2] = __low2float(h23);  vv[i][3] = __high2float(h23);
                }
#pragma unroll
                for (int tx = 0; tx < 3; tx++) {
                    float4 w = d4[(ty * 3 + tx) * 24 + c4];
#pragma unroll
                    for (int oxp = 0; oxp < 4; oxp++) {
                        a[oxp][0] = fmaf(w.x, vv[oxp + tx][0], a[oxp][0]);
                        a[oxp][1] = fmaf(w.y, vv[oxp + tx][1], a[oxp][1]);
                        a[oxp][2] = fmaf(w.z, vv[oxp + tx][2], a[oxp][2]);
                        a[oxp][3] = fmaf(w.w, vv[oxp + tx][3], a[oxp][3]);
                    }
                }
            }
#pragma unroll
            for (int oxp = 0; oxp < 4; oxp++) {
                float4 r = make_float4(to_tf32(a[oxp][0]), to_tf32(a[oxp][1]),
                                       to_tf32(a[oxp][2]), to_tf32(a[oxp][3]));
                *(float4*)&s_y[(py * 8 + qx0 + oxp) * 100 + c4 * 4] = r;
            }
        }
        __syncthreads();   // y ready; halo dead

        if (cc < 2) {
            stage_halo(cc + 1);
            CPA_COMMIT();
        }

        // --- pointwise via tf32 mma: this team's 48-channel K slice ---
#pragma unroll
        for (int s = 0; s < 6; s++) {
            const int k0 = team * 48 + s * 8;
            const unsigned int* yA =
                (const unsigned int*)&s_y[(mtb + lg) * 100 + k0 + lt];
            unsigned int a0 = yA[0],   a1 = yA[800];
            unsigned int a2 = yA[4],   a3 = yA[804];
#pragma unroll
            for (int j = 0; j < 4; j++) {
                unsigned int b0 = *(const unsigned int*)
                    &s_pw[(k0 + lt    ) * 72 + ntb + j * 8 + lg];
                unsigned int b1 = *(const unsigned int*)
                    &s_pw[(k0 + lt + 4) * 72 + ntb + j * 8 + lg];
                mma_tf32(acc[j], a0, a1, a2, a3, b0, b1);
            }
        }
    }
    __syncthreads();

    // split-K reduce across teams
    if (team == 1) {
        float* dst = &s_red[((warp & 7) * 32 + lane) * 16];
#pragma unroll
        for (int j = 0; j < 4; j++)
#pragma unroll
            for (int q = 0; q < 4; q++) dst[j * 4 + q] = acc[j][q];
    }
    __syncthreads();
    if (team == 0) {
        const float* src = &s_red[((warp & 7) * 32 + lane) * 16];
        const int px0 = mtb + lg, px1 = mtb + lg + 8;
#pragma unroll
        for (int j = 0; j < 4; j++) {
            int f0 = ntb + j * 8 + 2 * lt;
            float b0v = __ldg(&pw_b[gg * GF + f0]);
            float b1v = __ldg(&pw_b[gg * GF + f0 + 1]);
            s_out[px0 * OUTP + f0]     = acc[j][0] + src[j*4+0] + b0v;
            s_out[px0 * OUTP + f0 + 1] = acc[j][1] + src[j*4+1] + b1v;
            s_out[px1 * OUTP + f0]     = acc[j][2] + src[j*4+2] + b0v;
            s_out[px1 * OUTP + f0 + 1] = acc[j][3] + src[j*4+3] + b1v;
        }
    }
    __syncthreads();

    for (int i = tid; i < 4096; i += 512) {
        int p = i >> 6, f = i & 63;
        int py = p >> 3, px = p & 7;
        out[((size_t)((b * HH + ty0 + py) * WW) + tx0 + px) * (GG * GF)
            + gg * GF + f] = s_out[p * OUTP + f];
    }
}

// ---------------------------------------------------------------------------
extern "C" void kernel_launch(void* const* d_in, const int* in_sizes, int n_in,
                              void* d_out, int out_size)
{
    const float* x     = (const float*)d_in[0];
    const float* off_w = (const float*)d_in[1];
    const float* off_b = (const float*)d_in[2];
    const float* dw_w  = (const float*)d_in[3];
    const float* dw_b  = (const float*)d_in[4];
    const float* pw_w  = (const float*)d_in[5];
    const float* pw_b  = (const float*)d_in[6];
    float* out = (float*)d_out;

    cudaFuncSetAttribute(k_offsets, cudaFuncAttributeMaxDynamicSharedMemorySize,
                         OFF_SMEM_BYTES);
    cudaFuncSetAttribute(k_dwpw, cudaFuncAttributeMaxDynamicSharedMemorySize,
                         SM_BYTES);

    k_prep<<<(GG * SCH * GF + 255) / 256, 256>>>(pw_w);
    k_offsets<<<dim3(WW/32, HH/16, BB*GG), 256, OFF_SMEM_BYTES>>>(x, off_w, off_b);
    k_sample<<<dim3(NP / 8, GG), 256>>>(x);
    k_dwpw<<<dim3(WW / 8, HH / 8, BB * GG), 512, SM_BYTES>>>(
        dw_w, dw_b, pw_b, out);
}